// round 16
// baseline (speedup 1.0000x reference)
#include <cuda_runtime.h>
#include <cuda_fp16.h>
#include <math.h>

#define BB    8
#define NPG   5000
#define EPG   80000
#define NN    40000
#define GE    640000
#define HID   128
#define EMB   64

#define MMA_FP16(acc, a0, a1, a2, a3, b0, b1)                                   \
    asm volatile(                                                               \
        "mma.sync.aligned.m16n8k16.row.col.f32.f16.f16.f32 "                    \
        "{%0,%1,%2,%3},{%4,%5,%6,%7},{%8,%9},{%0,%1,%2,%3};"                    \
        : "+f"(acc[0]), "+f"(acc[1]), "+f"(acc[2]), "+f"(acc[3])                \
        : "r"(a0), "r"(a1), "r"(a2), "r"(a3), "r"(b0), "r"(b1))

// ---------------- scratch (static device arrays) ---------------------------
__device__ int   d_cnt[NPG], d_beg[NPG], d_cur[NPG];
__device__ int   d_csr[EPG + 16];
__device__ int   d_slot[EPG];
__device__ int   d_srcp[EPG + 16];
__device__ int   d_ctr;
__device__ int   d_bar1, d_bar2;
__device__ uint2 d_pk0[GE + 32], d_pk1[GE + 32];
__device__ __half d_nefp[GE * 16 + 256];
__device__ __half d_h0[NN * HID];
__device__ float d_s0s[NN], d_s0d[NN];
__device__ __half d_g0h[NN * HID];
__device__ __half d_h1[NN * EMB];
__device__ float d_s1s[NN], d_s1d[NN];
__device__ __half d_embh[NN * EMB];
__device__ __half d_A[NN * HID], d_Bm[NN * HID];
__device__ float d_D[BB * HID];
__device__ float d_wae0[16], d_wae1[16];
__device__ float d_was0[32], d_wad0[32];
__device__ float d_was1[128], d_wad1[128];
__device__ float d_psum[5000 * 64];
__device__ float d_pmaxf[5000 * 64];
__device__ __half  d_W1hT[256 * 64];
__device__ __half  d_W1gT[64 * 128];
__device__ unsigned d_WBf[16 * 2 * 32];

// ------------- k_pre -------------------------------------------------------
__global__ void k_pre(const float* __restrict__ We0, const float* __restrict__ ae0,
                      const float* __restrict__ We1, const float* __restrict__ ae1,
                      const float* __restrict__ W0,  const float* __restrict__ as0,
                      const float* __restrict__ ad0, const float* __restrict__ W1g,
                      const float* __restrict__ as1, const float* __restrict__ ad1,
                      const float* __restrict__ mW1)
{
    int t = blockIdx.x * blockDim.x + threadIdx.x;
    int stride = gridDim.x * blockDim.x;
    for (int i = t; i < NPG; i += stride) d_cnt[i] = 0;
    if (t == 0) { d_ctr = 0; d_bar1 = 0; d_bar2 = 0; }
    for (int i = t; i < 256 * 64; i += stride) {
        int col = i >> 6, k = i & 63;
        float w = (col < 128) ? mW1[k * 128 + col] : mW1[(64 + k) * 128 + (col - 128)];
        d_W1hT[i] = __float2half_rn(w);
    }
    for (int i = t; i < 64 * 128; i += stride) {
        int col = i >> 7, k = i & 127;
        d_W1gT[i] = __float2half_rn(W1g[k * 64 + col]);
    }
    for (int i = t; i < 1024; i += stride) {
        int q = i >> 5, L = i & 31;
        int nt = q >> 1, r = q & 1;
        int gr = L >> 2, tc = L & 3;
        int k0 = 2 * tc + 8 * r;
        int j  = nt * 8 + gr;
        __half2 h = __floats2half2_rn(mW1[(128 + k0) * 128 + j],
                                      mW1[(128 + k0 + 1) * 128 + j]);
        d_WBf[i] = *(unsigned*)&h;
    }
    if (blockIdx.x == 0) {
        int tt = threadIdx.x;
        if (tt < 16) {
            float s = 0.f;
            for (int c = 0; c < 128; c++) s += We0[tt * 128 + c] * ae0[c];
            d_wae0[tt] = s;
        } else if (tt < 32) {
            int k = tt - 16;
            float s = 0.f;
            for (int c = 0; c < 64; c++) s += We1[k * 64 + c] * ae1[c];
            d_wae1[k] = s;
        } else if (tt < 64) {
            int k = tt - 32;
            float s0 = 0.f, s1 = 0.f;
            for (int c = 0; c < 128; c++) {
                float w = W0[k * 128 + c];
                s0 += w * as0[c]; s1 += w * ad0[c];
            }
            d_was0[k] = s0; d_wad0[k] = s1;
        }
    } else if (blockIdx.x == 1) {
        int tt = threadIdx.x;
        if (tt < 128) {
            float s0 = 0.f, s1 = 0.f;
            for (int c = 0; c < 64; c++) {
                float w = W1g[tt * 64 + c];
                s0 += w * as1[c]; s1 += w * ad1[c];
            }
            d_was1[tt] = s0; d_wad1[tt] = s1;
        }
    }
}

// ---- CSR build in ONE kernel ------------------------------------------------
__device__ __forceinline__ void gbar(int* bar, int target)
{
    __syncthreads();
    if (threadIdx.x == 0) {
        __threadfence();
        atomicAdd(bar, 1);
        while (atomicAdd(bar, 0) < target) { }
    }
    __syncthreads();
}

__global__ void __launch_bounds__(256, 8) k_csr(const int* __restrict__ ei)
{
    int t = blockIdx.x * 256 + threadIdx.x;
    int stride = gridDim.x * 256;
    for (int el = t; el < EPG; el += stride)
        atomicAdd(&d_cnt[ei[EPG + el]], 1);
    gbar(&d_bar1, (int)gridDim.x);
    for (int n = t; n < NPG; n += stride) {
        int deg = d_cnt[n];
        int beg = atomicAdd(&d_ctr, deg);
        d_beg[n] = beg;
        d_cur[n] = beg;
    }
    gbar(&d_bar2, (int)gridDim.x);
    for (int el = t; el < EPG; el += stride) {
        int dst = ei[EPG + el];
        int pos = atomicAdd(&d_cur[dst], 1);
        d_csr[pos] = el;
        d_slot[el] = pos;
        d_srcp[pos] = ei[el];
    }
}

// ------- node features: LN + proj0 + folded s0 scalars (warp per node) -------
__global__ void k_nodefeat(const float* __restrict__ x, const float* __restrict__ ng,
                           const float* __restrict__ nb, const float* __restrict__ W)
{
    int warp = threadIdx.x >> 5, lane = threadIdx.x & 31;
    int n = blockIdx.x * 8 + warp;
    float v = x[n * 32 + lane];
    float mu = v;
    #pragma unroll
    for (int o = 16; o; o >>= 1) mu += __shfl_xor_sync(~0u, mu, o);
    mu *= (1.f / 32.f);
    float d = v - mu;
    float var = d * d;
    #pragma unroll
    for (int o = 16; o; o >>= 1) var += __shfl_xor_sync(~0u, var, o);
    var *= (1.f / 32.f);
    float y = d * rsqrtf(var + 1e-5f) * ng[lane] + nb[lane];

    float ps = y * d_was0[lane], pd = y * d_wad0[lane];
    #pragma unroll
    for (int o = 16; o; o >>= 1) {
        ps += __shfl_xor_sync(~0u, ps, o);
        pd += __shfl_xor_sync(~0u, pd, o);
    }
    if (lane == 0) { d_s0s[n] = ps; d_s0d[n] = pd; }

    float a0 = 0.f, a1 = 0.f, a2 = 0.f, a3 = 0.f;
    #pragma unroll 8
    for (int k = 0; k < 32; k++) {
        float yk = __shfl_sync(~0u, y, k);
        float4 w = *(const float4*)(W + k * 128 + lane * 4);
        a0 += yk * w.x; a1 += yk * w.y; a2 += yk * w.z; a3 += yk * w.w;
    }
    __half2 h01 = __floats2half2_rn(a0, a1);
    __half2 h23 = __floats2half2_rn(a2, a3);
    uint2 u; u.x = *(unsigned*)&h01; u.y = *(unsigned*)&h23;
    *(uint2*)(d_h0 + (size_t)n * 128 + lane * 4) = u;
}

// ------- edge features: LN + logit terms; s0s[src] folded into ee0 -----------
__global__ void k_edgefeat(const float* __restrict__ ea, const float* __restrict__ eg,
                           const float* __restrict__ eb, const int* __restrict__ ei)
{
    __shared__ float sg[16], sb[16], sw0[16], sw1[16];
    if (threadIdx.x < 16) {
        sg[threadIdx.x] = eg[threadIdx.x];
        sb[threadIdx.x] = eb[threadIdx.x];
        sw0[threadIdx.x] = d_wae0[threadIdx.x];
        sw1[threadIdx.x] = d_wae1[threadIdx.x];
    }
    __syncthreads();
    int ge = blockIdx.x * 256 + threadIdx.x;
    int bb = ge / EPG;
    int el = ge - bb * EPG;
    int pos = d_slot[el];
    int srcl = ei[el];
    size_t base = (size_t)bb * EPG + pos;
    float s0src = d_s0s[bb * NPG + srcl];     // folded into ee0

    const float4* rp = (const float4*)(ea + (size_t)ge * 16);
    float4 q[4];
    q[0] = rp[0]; q[1] = rp[1]; q[2] = rp[2]; q[3] = rp[3];
    float* v = (float*)q;
    float mu = 0.f;
    #pragma unroll
    for (int k = 0; k < 16; k++) mu += v[k];
    mu *= (1.f / 16.f);
    float var = 0.f;
    #pragma unroll
    for (int k = 0; k < 16; k++) { float d = v[k] - mu; var += d * d; }
    var *= (1.f / 16.f);
    float r = rsqrtf(var + 1e-5f);
    float e0 = 0.f, e1 = 0.f;
    __half2 hh[8];
    #pragma unroll
    for (int k = 0; k < 16; k += 2) {
        float y0 = (v[k] - mu) * r * sg[k] + sb[k];
        float y1 = (v[k + 1] - mu) * r * sg[k + 1] + sb[k + 1];
        e0 += y0 * sw0[k] + y1 * sw0[k + 1];
        e1 += y0 * sw1[k] + y1 * sw1[k + 1];
        hh[k >> 1] = __floats2half2_rn(y0, y1);
    }
    uint4* wp = (uint4*)(d_nefp + base * 16);
    wp[0] = *(uint4*)&hh[0];
    wp[1] = *(uint4*)&hh[4];
    d_pk0[base] = make_uint2(__float_as_uint(e0 + s0src), (unsigned)srcl);
    d_pk1[base] = make_uint2(__float_as_uint(e1), (unsigned)srcl);
}

// -------- fp16 gather helper -------------------------------------------------
template<int K>
__device__ __forceinline__ void gatherH(float* acc, const __half* __restrict__ h,
                                        int S, float A, int lane)
{
    if constexpr (K == 4) {
        uint2 u = *(const uint2*)(h + (size_t)S * 128 + lane * 4);
        float2 f01 = __half22float2(*(__half2*)&u.x);
        float2 f23 = __half22float2(*(__half2*)&u.y);
        acc[0] += A * f01.x; acc[1] += A * f01.y;
        acc[2] += A * f23.x; acc[3] += A * f23.y;
    } else {
        __half2 hv = *(const __half2*)(h + (size_t)S * 64 + lane * 2);
        float2 f = __half22float2(hv);
        acc[0] += A * f.x; acc[1] += A * f.y;
    }
}

// -------- shared softmax+gather core; FOLDED => ss already inside pk.x --------
template<int K, bool FOLDED>
__device__ __forceinline__ void agg_core(float* acc, const __half* __restrict__ h,
                                         const float* __restrict__ ss,
                                         const uint2* __restrict__ pk,
                                         float sdv, int b, int deg,
                                         size_t ebase, int lane)
{
    int bN = b * NPG;
    if (deg <= 32) {
        int src = 0;
        float lg = -1e30f;
        if (lane < deg) {
            uint2 p = pk[ebase + lane];
            src = bN + (int)p.y;
            float base = FOLDED ? sdv : (ss[src] + sdv);
            lg = base + __uint_as_float(p.x);
            lg = lg > 0.f ? lg : 0.2f * lg;
        }
        float M = lg;
        #pragma unroll
        for (int o = 16; o; o >>= 1) M = fmaxf(M, __shfl_xor_sync(~0u, M, o));
        float ex = (lane < deg) ? __expf(lg - M) : 0.f;
        float sm = ex;
        #pragma unroll
        for (int o = 16; o; o >>= 1) sm += __shfl_xor_sync(~0u, sm, o);
        float alpha = ex / (sm + 1e-16f);
        for (int j = 0; j < deg; j += 8) {
            #pragma unroll
            for (int q = 0; q < 8; q++) {
                float A = __shfl_sync(~0u, alpha, j + q);
                int S   = __shfl_sync(~0u, src, j + q);
                gatherH<K>(acc, h, S, A, lane);
            }
        }
    } else {
        float m = -1e30f, sm = 0.f;
        for (int i = lane; i < deg; i += 32) {
            uint2 p = pk[ebase + i];
            float base = FOLDED ? sdv : (ss[bN + (int)p.y] + sdv);
            float lg = base + __uint_as_float(p.x);
            lg = lg > 0.f ? lg : 0.2f * lg;
            float nm = fmaxf(m, lg);
            sm = sm * __expf(m - nm) + __expf(lg - nm);
            m = nm;
        }
        float M = m;
        #pragma unroll
        for (int o = 16; o; o >>= 1) M = fmaxf(M, __shfl_xor_sync(~0u, M, o));
        sm *= __expf(m - M);
        #pragma unroll
        for (int o = 16; o; o >>= 1) sm += __shfl_xor_sync(~0u, sm, o);
        float inv = 1.f / (sm + 1e-16f);
        for (int basei = 0; basei < deg; basei += 32) {
            int i = basei + lane;
            float alpha = 0.f;
            int src = 0;
            if (i < deg) {
                uint2 p = pk[ebase + i];
                src = bN + (int)p.y;
                float base = FOLDED ? sdv : (ss[src] + sdv);
                float lg = base + __uint_as_float(p.x);
                lg = lg > 0.f ? lg : 0.2f * lg;
                alpha = __expf(lg - M) * inv;
            }
            int cnt = min(32, deg - basei);
            for (int j = 0; j < cnt; j += 8) {
                #pragma unroll
                for (int q = 0; q < 8; q++) {
                    float A = __shfl_sync(~0u, alpha, j + q);
                    int S   = __shfl_sync(~0u, src, j + q);
                    gatherH<K>(acc, h, S, A, lane);
                }
            }
        }
    }
}

// -------- agg0 -----------------------------------------------------------------
__global__ void __launch_bounds__(256, 8) k_agg0(const float* __restrict__ bias)
{
    int warp = threadIdx.x >> 5, lane = threadIdx.x & 31;
    int n = blockIdx.x * 8 + warp;
    int b = n / NPG, ln = n - b * NPG;
    int beg = d_beg[ln], deg = d_cnt[ln];
    size_t ebase = (size_t)b * EPG + beg;
    float acc[4] = {0.f, 0.f, 0.f, 0.f};
    if (deg > 0)
        agg_core<4, true>(acc, d_h0, d_s0s, d_pk0, d_s0d[n], b, deg, ebase, lane);

    float v[4];
    float ps = 0.f, pd = 0.f;
    #pragma unroll
    for (int u = 0; u < 4; u++) {
        float t = acc[u] + bias[lane * 4 + u];
        t = t > 0.f ? t : (__expf(t) - 1.f);
        v[u] = t;
        ps += t * d_was1[lane * 4 + u];
        pd += t * d_wad1[lane * 4 + u];
    }
    #pragma unroll
    for (int o = 16; o; o >>= 1) {
        ps += __shfl_xor_sync(~0u, ps, o);
        pd += __shfl_xor_sync(~0u, pd, o);
    }
    if (lane == 0) { d_s1s[n] = ps; d_s1d[n] = pd; }
    __half2 h01 = __floats2half2_rn(v[0], v[1]);
    __half2 h23 = __floats2half2_rn(v[2], v[3]);
    uint2 u; u.x = *(unsigned*)&h01; u.y = *(unsigned*)&h23;
    *(uint2*)(d_g0h + (size_t)n * 128 + lane * 4) = u;
}

// -------- proj1 via tensor cores ----------------------------------------------
__global__ void k_proj1mma()
{
    __shared__ __half sW[64 * 136];
    __shared__ __half sE[32 * 136];
    int t = threadIdx.x;
    int n0 = blockIdx.x * 32;
    {
        const uint4* src = (const uint4*)d_W1gT;
        uint4* dst = (uint4*)sW;
        for (int i = t; i < 64 * 16; i += 256) {
            int col = i >> 4, ch = i & 15;
            dst[col * 17 + ch] = src[col * 16 + ch];
        }
    }
    {
        const uint4* src = (const uint4*)(d_g0h + (size_t)n0 * 128);
        uint4* dst = (uint4*)sE;
        for (int i = t; i < 32 * 16; i += 256) {
            int row = i >> 4, ch = i & 15;
            dst[row * 17 + ch] = src[row * 16 + ch];
        }
    }
    __syncthreads();

    int warp = t >> 5, lane = t & 31;
    int s = warp & 1;
    int g = warp >> 1;
    int gr = lane >> 2, tc = lane & 3;

    float acc[2][4];
    #pragma unroll
    for (int tt = 0; tt < 2; tt++)
        #pragma unroll
        for (int u = 0; u < 4; u++) acc[tt][u] = 0.f;

    #pragma unroll
    for (int kk = 0; kk < 128; kk += 16) {
        unsigned a0 = *(const unsigned*)(sE + (s * 16 + gr) * 136 + kk + 2 * tc);
        unsigned a1 = *(const unsigned*)(sE + (s * 16 + gr + 8) * 136 + kk + 2 * tc);
        unsigned a2 = *(const unsigned*)(sE + (s * 16 + gr) * 136 + kk + 2 * tc + 8);
        unsigned a3 = *(const unsigned*)(sE + (s * 16 + gr + 8) * 136 + kk + 2 * tc + 8);
        #pragma unroll
        for (int tt = 0; tt < 2; tt++) {
            int col = g * 16 + tt * 8 + gr;
            unsigned b0 = *(const unsigned*)(sW + col * 136 + kk + 2 * tc);
            unsigned b1 = *(const unsigned*)(sW + col * 136 + kk + 2 * tc + 8);
            MMA_FP16(acc[tt], a0, a1, a2, a3, b0, b1);
        }
    }
    #pragma unroll
    for (int tt = 0; tt < 2; tt++) {
        int c = g * 16 + tt * 8 + 2 * tc;
        int r0 = n0 + s * 16 + gr, r1 = r0 + 8;
        __half2 h0 = __floats2half2_rn(acc[tt][0], acc[tt][1]);
        __half2 h1 = __floats2half2_rn(acc[tt][2], acc[tt][3]);
        *(__half2*)(d_h1 + (size_t)r0 * 64 + c) = h0;
        *(__half2*)(d_h1 + (size_t)r1 * 64 + c) = h1;
    }
}

// -------- agg1 fused with pooling partials; emb written fp16 ------------------
__global__ void __launch_bounds__(256, 8) k_agg1(const float* __restrict__ bias)
{
    __shared__ float semb[8][64];
    int warp = threadIdx.x >> 5, lane = threadIdx.x & 31;
    int n = blockIdx.x * 8 + warp;
    int b = n / NPG, ln = n - b * NPG;
    int beg = d_beg[ln], deg = d_cnt[ln];
    size_t ebase = (size_t)b * EPG + beg;
    float acc[2] = {0.f, 0.f};
    if (deg > 0)
        agg_core<2, false>(acc, d_h1, d_s1s, d_pk1, d_s1d[n], b, deg, ebase, lane);

    float v0 = acc[0] + bias[lane * 2];
    float v1 = acc[1] + bias[lane * 2 + 1];
    __half2 hh = __floats2half2_rn(v0, v1);
    *(__half2*)(d_embh + (size_t)n * 64 + lane * 2) = hh;
    semb[warp][lane * 2] = v0;
    semb[warp][lane * 2 + 1] = v1;
    __syncthreads();
    int t = threadIdx.x;
    if (t < 64) {
        float s = 0.f, m = -1e30f;
        #pragma unroll
        for (int r = 0; r < 8; r++) {
            float x = semb[r][t];
            s += x; m = fmaxf(m, x);
        }
        d_psum[blockIdx.x * 64 + t] = s;
        d_pmaxf[blockIdx.x * 64 + t] = m;
    }
}

// ------ k_ABD ------------------------------------------------------------------
__global__ void k_ABD(const float* __restrict__ W1, const float* __restrict__ b1)
{
    __shared__ __half sW[256 * 72];
    __shared__ __half sE[32 * 72];
    __shared__ float red[256];
    __shared__ float ctx[128];
    int t = threadIdx.x;

    if (blockIdx.x >= 1250) {
        int g = blockIdx.x - 1250;
        int c = t & 63, r = t >> 6;
        float s = 0.f, m = -1e30f;
        for (int i = r; i < 625; i += 4) {
            int idx = (g * 625 + i) * 64 + c;
            s += d_psum[idx];
            m = fmaxf(m, d_pmaxf[idx]);
        }
        red[t] = s;
        __syncthreads();
        if (r < 2) red[t] += red[t + 128];
        __syncthreads();
        if (r == 0) ctx[c] = (red[c] + red[c + 64]) * (1.f / NPG);
        __syncthreads();
        red[t] = m;
        __syncthreads();
        if (r < 2) red[t] = fmaxf(red[t], red[t + 128]);
        __syncthreads();
        if (r == 0) ctx[64 + c] = fmaxf(red[c], red[c + 64]);
        __syncthreads();
        int c2 = t & 127, p = t >> 7;
        float acc = 0.f;
        for (int k = p * 64; k < p * 64 + 64; k++)
            acc += ctx[k] * W1[(144 + k) * 128 + c2];
        red[t] = acc;
        __syncthreads();
        if (p == 0) d_D[g * 128 + c2] = b1[c2] + red[c2] + red[128 + c2];
        return;
    }

    int n0 = blockIdx.x * 32;
    {
        const uint4* src = (const uint4*)d_W1hT;
        uint4* dst = (uint4*)sW;
        for (int i = t; i < 256 * 8; i += 256) {
            int col = i >> 3, ch = i & 7;
            dst[col * 9 + ch] = src[col * 8 + ch];
        }
    }
    {
        const uint4* src = (const uint4*)(d_embh + (size_t)n0 * 64);
        uint4* dst = (uint4*)sE;
        for (int i = t; i < 32 * 8; i += 256) {
            int row = i >> 3, ch = i & 7;
            dst[row * 9 + ch] = src[row * 8 + ch];
        }
    }
    __syncthreads();

    int warp = t >> 5, lane = t & 31;
    int s = warp & 1;
    int g = warp >> 1;
    int gr = lane >> 2, tc = lane & 3;

    float acc[8][4];
    #pragma unroll
    for (int tt = 0; tt < 8; tt++)
        #pragma unroll
        for (int u = 0; u < 4; u++) acc[tt][u] = 0.f;

    #pragma unroll
    for (int kk = 0; kk < 64; kk += 16) {
        unsigned a0 = *(const unsigned*)(sE + (s * 16 + gr) * 72 + kk + 2 * tc);
        unsigned a1 = *(const unsigned*)(sE + (s * 16 + gr + 8) * 72 + kk + 2 * tc);
        unsigned a2 = *(const unsigned*)(sE + (s * 16 + gr) * 72 + kk + 2 * tc + 8);
        unsigned a3 = *(const unsigned*)(sE + (s * 16 + gr + 8) * 72 + kk + 2 * tc + 8);
        #pragma unroll
        for (int tt = 0; tt < 8; tt++) {
            int col = g * 64 + tt * 8 + gr;
            unsigned b0 = *(const unsigned*)(sW + col * 72 + kk + 2 * tc);
            unsigned b1 = *(const unsigned*)(sW + col * 72 + kk + 2 * tc + 8);
            MMA_FP16(acc[tt], a0, a1, a2, a3, b0, b1);
        }
    }
    #pragma unroll
    for (int tt = 0; tt < 8; tt++) {
        int c = g * 64 + tt * 8 + 2 * tc;
        int r0 = n0 + s * 16 + gr, r1 = r0 + 8;
        __half2 h0 = __floats2half2_rn(acc[tt][0], acc[tt][1]);
        __half2 h1 = __floats2half2_rn(acc[tt][2], acc[tt][3]);
        if (c < 128) {
            *(__half2*)(d_A + (size_t)r0 * 128 + c) = h0;
            *(__half2*)(d_A + (size_t)r1 * 128 + c) = h1;
        } else {
            *(__half2*)(d_Bm + (size_t)r0 * 128 + c - 128) = h0;
            *(__half2*)(d_Bm + (size_t)r1 * 128 + c - 128) = h1;
        }
    }
}

// ------ k_final -----------------------------------------------------------------
__global__ void k_final(const float* __restrict__ W2, const float* __restrict__ b2,
                        float* __restrict__ out)
{
    __shared__ __half sEF[8][256];
    __shared__ __half sA[8][16 * 136];
    __shared__ float  sbase[8][128];
    __shared__ float  sV[128];
    int t = threadIdx.x;
    if (t < 128) sV[t] = W2[t];
    __syncthreads();

    int warp = t >> 5, lane = t & 31;
    int gr = lane >> 2, tc = lane & 3;
    float bias2 = b2[0];

    unsigned wb[32];
    #pragma unroll
    for (int q = 0; q < 32; q++) wb[q] = d_WBf[q * 32 + lane];

    __half* myEF = sEF[warp];
    __half* myA  = sA[warp];
    float*  myB  = sbase[warp];

    for (int n = blockIdx.x * 8 + warp; n < NN; n += gridDim.x * 8) {
        int b = n / NPG, ln = n - b * NPG;
        int beg = d_beg[ln], deg = d_cnt[ln];
        if (deg == 0) continue;
        int bNPG = b * NPG;
        size_t bEPG = (size_t)b * EPG;
        size_t ebase = bEPG + beg;

        {
            int j0 = lane * 4;
            uint2 ub = *(const uint2*)(d_Bm + (size_t)n * 128 + j0);
            float2 blo = __half22float2(*(__half2*)&ub.x);
            float2 bhi = __half22float2(*(__half2*)&ub.y);
            float4 vd = *(const float4*)(d_D + b * 128 + j0);
            float4 bs;
            bs.x = blo.x + vd.x; bs.y = blo.y + vd.y;
            bs.z = bhi.x + vd.z; bs.w = bhi.y + vd.w;
            *(float4*)(myB + j0) = bs;
        }
        __syncwarp();

        for (int i = 0; i < deg; i += 16) {
            {
                uint4 v = *(const uint4*)(d_nefp + (ebase + i) * 16 + lane * 8);
                *(uint4*)(myEF + lane * 8) = v;
            }
            int sl = d_srcp[beg + min(i + (lane & 15), deg - 1)];
            __syncwarp();
            #pragma unroll
            for (int j = 0; j < 8; j++) {
                int r = 2 * j + (lane >> 4);
                int sr = __shfl_sync(~0u, sl, r);
                uint4 av = *(const uint4*)(d_A + (size_t)(bNPG + sr) * 128 + (lane & 15) * 8);
                *(uint4*)(myA + r * 136 + (lane & 15) * 8) = av;
            }
            __syncwarp();

            unsigned a0 = *(const unsigned*)(myEF + gr * 16 + 2 * tc);
            unsigned a1 = *(const unsigned*)(myEF + (gr + 8) * 16 + 2 * tc);
            unsigned a2 = *(const unsigned*)(myEF + gr * 16 + 2 * tc + 8);
            unsigned a3 = *(const unsigned*)(myEF + (gr + 8) * 16 + 2 * tc + 8);

            float rowlo = 0.f, rowhi = 0.f;
            #pragma unroll
            for (int nt = 0; nt < 16; nt++) {
                float c[4] = {0.f, 0.f, 0.f, 0.f};
                MMA_FP16(c, a0, a1, a2, a3, wb[nt * 2], wb[nt * 2 + 1]);
                int col = 2 * tc + 8 * nt;
                unsigned alo = *(const unsigned*)(myA + gr * 136 + col);
                unsigned ahi = *(const unsigned*)(myA + (gr + 8) * 136 + col);
                float2 fa = __half22float2(*(__half2*)&alo);
                float2 fh = __half22float2(*(__half2*)&ahi);
                float2 bs = *(const float2*)(myB + col);
                float2 w2 = *(const float2*)(sV + col);
                float v0 = c[0] + fa.x + bs.x;
                float v1 = c[1] + fa.y + bs.y;
                float v2 = c[2] + fh.x + bs.x;
                float v3 = c[3] + fh.y + bs.y;
                rowlo += fmaxf(v0, 0.f) * w2.x + fmaxf(v1, 0.f) * w2.y;
                rowhi += fmaxf(v2, 0.f) * w2.x + fmaxf(v3, 0.f) * w2.y;
            }
            rowlo += __shfl_xor_sync(~0u, rowlo, 1);
            rowlo += __shfl_xor_sync(~0u, rowlo, 2);
            rowhi += __shfl_xor_sync(~0u, rowhi, 1);
            rowhi += __shfl_xor_sync(~0u, rowhi, 2);
            if (tc == 0) {
                int e0 = i + gr, e1 = i + gr + 8;
                if (e0 < deg) out[bEPG + d_csr[beg + e0]] = rowlo + bias2;
                if (e1 < deg) out[bEPG + d_csr[beg + e1]] = rowhi + bias2;
            }
            __syncwarp();
        }
    }
}

// ---------------------------------------------------------------------------
extern "C" void kernel_launch(void* const* d_in, const int* in_sizes, int n_in,
                              void* d_out, int out_size)
{
    const float* node_x    = (const float*)d_in[0];
    const float* edge_attr = (const float*)d_in[1];
    const int*   edge_idx  = (const int*)  d_in[2];
    const float* ln_ng     = (const float*)d_in[3];
    const float* ln_nb     = (const float*)d_in[4];
    const float* ln_eg     = (const float*)d_in[5];
    const float* ln_eb     = (const float*)d_in[6];
    const float* g0_W      = (const float*)d_in[7];
    const float* g0_We     = (const float*)d_in[8];
    const float* g0_asrc   = (const float*)d_in[9];
    const float* g0_adst   = (const float*)d_in[10];
    const float* g0_ae     = (const float*)d_in[11];
    const float* g0_b      = (const float*)d_in[12];
    const float* g1_W      = (const float*)d_in[13];
    const float* g1_We     = (const float*)d_in[14];
    const float* g1_asrc   = (const float*)d_in[15];
    const float* g1_adst   = (const float*)d_in[16];
    const float* g1_ae     = (const float*)d_in[17];
    const float* g1_b      = (const float*)d_in[18];
    const float* mlp_W1    = (const float*)d_in[19];
    const float* mlp_b1    = (const float*)d_in[20];
    const float* mlp_W2    = (const float*)d_in[21];
    const float* mlp_b2    = (const float*)d_in[22];
    float* out = (float*)d_out;

    k_pre<<<148, 256>>>(g0_We, g0_ae, g1_We, g1_ae,
                        g0_W, g0_asrc, g0_adst, g1_W, g1_asrc, g1_adst, mlp_W1);
    k_nodefeat<<<NN / 8, 256>>>(node_x, ln_ng, ln_nb, g0_W);
    k_csr<<<592, 256>>>(edge_idx);
    k_edgefeat<<<GE / 256, 256>>>(edge_attr, ln_eg, ln_eb, edge_idx);
    k_agg0<<<5000, 256>>>(g0_b);
    k_proj1mma<<<NN / 32, 256>>>();
    k_agg1<<<5000, 256>>>(g1_b);
    k_ABD<<<1258, 256>>>(mlp_W1, mlp_b1);
    k_final<<<740, 256>>>(mlp_W2, mlp_b2, out);
}

// round 17
// speedup vs baseline: 1.0134x; 1.0134x over previous
#include <cuda_runtime.h>
#include <cuda_fp16.h>
#include <math.h>

#define BB    8
#define NPG   5000
#define EPG   80000
#define NN    40000
#define GE    640000
#define HID   128
#define EMB   64

#define MMA_FP16(acc, a0, a1, a2, a3, b0, b1)                                   \
    asm volatile(                                                               \
        "mma.sync.aligned.m16n8k16.row.col.f32.f16.f16.f32 "                    \
        "{%0,%1,%2,%3},{%4,%5,%6,%7},{%8,%9},{%0,%1,%2,%3};"                    \
        : "+f"(acc[0]), "+f"(acc[1]), "+f"(acc[2]), "+f"(acc[3])                \
        : "r"(a0), "r"(a1), "r"(a2), "r"(a3), "r"(b0), "r"(b1))

// ---------------- scratch (static device arrays) ---------------------------
__device__ int   d_cnt[NPG], d_beg[NPG], d_cur[NPG];
__device__ int   d_csr[EPG + 16];
__device__ int   d_slot[EPG];
__device__ int   d_srcp[EPG + 16];
__device__ int   d_ctr;
__device__ int   d_bar1, d_bar2;
__device__ uint2 d_pk0[GE + 32], d_pk1[GE + 32];
__device__ __half d_nefp[GE * 16 + 256];
__device__ __half d_h0[NN * HID];
__device__ float d_s0s[NN], d_s0d[NN];
__device__ __half d_g0h[NN * HID];
__device__ __half d_h1[NN * EMB];
__device__ float d_s1s[NN], d_s1d[NN];
__device__ __half d_embh[NN * EMB];
__device__ __half d_A[NN * HID], d_Bm[NN * HID];
__device__ float d_D[BB * HID];
__device__ float d_wae0[16], d_wae1[16];
__device__ float d_was0[32], d_wad0[32];
__device__ float d_was1[128], d_wad1[128];
__device__ float d_psum[5000 * 64];
__device__ float d_pmaxf[5000 * 64];
__device__ __half  d_W1hT[256 * 64];
__device__ __half  d_W1gT[64 * 128];
__device__ unsigned d_WBf[16 * 2 * 32];

// ------------- k_pre -------------------------------------------------------
__global__ void k_pre(const float* __restrict__ We0, const float* __restrict__ ae0,
                      const float* __restrict__ We1, const float* __restrict__ ae1,
                      const float* __restrict__ W0,  const float* __restrict__ as0,
                      const float* __restrict__ ad0, const float* __restrict__ W1g,
                      const float* __restrict__ as1, const float* __restrict__ ad1,
                      const float* __restrict__ mW1)
{
    int t = blockIdx.x * blockDim.x + threadIdx.x;
    int stride = gridDim.x * blockDim.x;
    for (int i = t; i < NPG; i += stride) d_cnt[i] = 0;
    if (t == 0) { d_ctr = 0; d_bar1 = 0; d_bar2 = 0; }
    for (int i = t; i < 256 * 64; i += stride) {
        int col = i >> 6, k = i & 63;
        float w = (col < 128) ? mW1[k * 128 + col] : mW1[(64 + k) * 128 + (col - 128)];
        d_W1hT[i] = __float2half_rn(w);
    }
    for (int i = t; i < 64 * 128; i += stride) {
        int col = i >> 7, k = i & 127;
        d_W1gT[i] = __float2half_rn(W1g[k * 64 + col]);
    }
    for (int i = t; i < 1024; i += stride) {
        int q = i >> 5, L = i & 31;
        int nt = q >> 1, r = q & 1;
        int gr = L >> 2, tc = L & 3;
        int k0 = 2 * tc + 8 * r;
        int j  = nt * 8 + gr;
        __half2 h = __floats2half2_rn(mW1[(128 + k0) * 128 + j],
                                      mW1[(128 + k0 + 1) * 128 + j]);
        d_WBf[i] = *(unsigned*)&h;
    }
    if (blockIdx.x == 0) {
        int tt = threadIdx.x;
        if (tt < 16) {
            float s = 0.f;
            for (int c = 0; c < 128; c++) s += We0[tt * 128 + c] * ae0[c];
            d_wae0[tt] = s;
        } else if (tt < 32) {
            int k = tt - 16;
            float s = 0.f;
            for (int c = 0; c < 64; c++) s += We1[k * 64 + c] * ae1[c];
            d_wae1[k] = s;
        } else if (tt < 64) {
            int k = tt - 32;
            float s0 = 0.f, s1 = 0.f;
            for (int c = 0; c < 128; c++) {
                float w = W0[k * 128 + c];
                s0 += w * as0[c]; s1 += w * ad0[c];
            }
            d_was0[k] = s0; d_wad0[k] = s1;
        }
    } else if (blockIdx.x == 1) {
        int tt = threadIdx.x;
        if (tt < 128) {
            float s0 = 0.f, s1 = 0.f;
            for (int c = 0; c < 64; c++) {
                float w = W1g[tt * 64 + c];
                s0 += w * as1[c]; s1 += w * ad1[c];
            }
            d_was1[tt] = s0; d_wad1[tt] = s1;
        }
    }
}

// ---- CSR build in ONE kernel ------------------------------------------------
__device__ __forceinline__ void gbar(int* bar, int target)
{
    __syncthreads();
    if (threadIdx.x == 0) {
        __threadfence();
        atomicAdd(bar, 1);
        while (atomicAdd(bar, 0) < target) { }
    }
    __syncthreads();
}

__global__ void __launch_bounds__(256, 8) k_csr(const int* __restrict__ ei)
{
    int t = blockIdx.x * 256 + threadIdx.x;
    int stride = gridDim.x * 256;
    for (int el = t; el < EPG; el += stride)
        atomicAdd(&d_cnt[ei[EPG + el]], 1);
    gbar(&d_bar1, (int)gridDim.x);
    for (int n = t; n < NPG; n += stride) {
        int deg = d_cnt[n];
        int beg = atomicAdd(&d_ctr, deg);
        d_beg[n] = beg;
        d_cur[n] = beg;
    }
    gbar(&d_bar2, (int)gridDim.x);
    for (int el = t; el < EPG; el += stride) {
        int dst = ei[EPG + el];
        int pos = atomicAdd(&d_cur[dst], 1);
        d_csr[pos] = el;
        d_slot[el] = pos;
        d_srcp[pos] = ei[el];
    }
}

// ------- fused feature kernel ------------------------------------------------
__global__ void k_feat(const float* __restrict__ ea, const float* __restrict__ eg,
                       const float* __restrict__ eb, const float* __restrict__ x,
                       const float* __restrict__ ng, const float* __restrict__ nb,
                       const float* __restrict__ W, const int* __restrict__ ei)
{
    __shared__ float sg[16], sb[16], sw0[16], sw1[16];
    if (blockIdx.x < 2500) {
        if (threadIdx.x < 16) {
            sg[threadIdx.x] = eg[threadIdx.x];
            sb[threadIdx.x] = eb[threadIdx.x];
            sw0[threadIdx.x] = d_wae0[threadIdx.x];
            sw1[threadIdx.x] = d_wae1[threadIdx.x];
        }
        __syncthreads();
        int ge = blockIdx.x * 256 + threadIdx.x;
        int bb = ge / EPG;
        int el = ge - bb * EPG;
        int pos = d_slot[el];
        int srcl = ei[el];
        size_t base = (size_t)bb * EPG + pos;

        const float4* rp = (const float4*)(ea + (size_t)ge * 16);
        float4 q[4];
        q[0] = rp[0]; q[1] = rp[1]; q[2] = rp[2]; q[3] = rp[3];
        float* v = (float*)q;
        float mu = 0.f;
        #pragma unroll
        for (int k = 0; k < 16; k++) mu += v[k];
        mu *= (1.f / 16.f);
        float var = 0.f;
        #pragma unroll
        for (int k = 0; k < 16; k++) { float d = v[k] - mu; var += d * d; }
        var *= (1.f / 16.f);
        float r = rsqrtf(var + 1e-5f);
        float e0 = 0.f, e1 = 0.f;
        __half2 hh[8];
        #pragma unroll
        for (int k = 0; k < 16; k += 2) {
            float y0 = (v[k] - mu) * r * sg[k] + sb[k];
            float y1 = (v[k + 1] - mu) * r * sg[k + 1] + sb[k + 1];
            e0 += y0 * sw0[k] + y1 * sw0[k + 1];
            e1 += y0 * sw1[k] + y1 * sw1[k + 1];
            hh[k >> 1] = __floats2half2_rn(y0, y1);
        }
        uint4* wp = (uint4*)(d_nefp + base * 16);
        wp[0] = *(uint4*)&hh[0];
        wp[1] = *(uint4*)&hh[4];
        d_pk0[base] = make_uint2(__float_as_uint(e0), (unsigned)srcl);
        d_pk1[base] = make_uint2(__float_as_uint(e1), (unsigned)srcl);
    } else {
        int warp = threadIdx.x >> 5, lane = threadIdx.x & 31;
        int n = (blockIdx.x - 2500) * 8 + warp;
        float v = x[n * 32 + lane];
        float mu = v;
        #pragma unroll
        for (int o = 16; o; o >>= 1) mu += __shfl_xor_sync(~0u, mu, o);
        mu *= (1.f / 32.f);
        float d = v - mu;
        float var = d * d;
        #pragma unroll
        for (int o = 16; o; o >>= 1) var += __shfl_xor_sync(~0u, var, o);
        var *= (1.f / 32.f);
        float y = d * rsqrtf(var + 1e-5f) * ng[lane] + nb[lane];

        float ps = y * d_was0[lane], pd = y * d_wad0[lane];
        #pragma unroll
        for (int o = 16; o; o >>= 1) {
            ps += __shfl_xor_sync(~0u, ps, o);
            pd += __shfl_xor_sync(~0u, pd, o);
        }
        if (lane == 0) { d_s0s[n] = ps; d_s0d[n] = pd; }

        float a0 = 0.f, a1 = 0.f, a2 = 0.f, a3 = 0.f;
        #pragma unroll 8
        for (int k = 0; k < 32; k++) {
            float yk = __shfl_sync(~0u, y, k);
            float4 w = *(const float4*)(W + k * 128 + lane * 4);
            a0 += yk * w.x; a1 += yk * w.y; a2 += yk * w.z; a3 += yk * w.w;
        }
        __half2 h01 = __floats2half2_rn(a0, a1);
        __half2 h23 = __floats2half2_rn(a2, a3);
        uint2 u; u.x = *(unsigned*)&h01; u.y = *(unsigned*)&h23;
        *(uint2*)(d_h0 + (size_t)n * 128 + lane * 4) = u;
    }
}

// -------- fp16 gather helper -------------------------------------------------
template<int K>
__device__ __forceinline__ void gatherH(float* acc, const __half* __restrict__ h,
                                        int S, float A, int lane)
{
    if constexpr (K == 4) {
        uint2 u = *(const uint2*)(h + (size_t)S * 128 + lane * 4);
        float2 f01 = __half22float2(*(__half2*)&u.x);
        float2 f23 = __half22float2(*(__half2*)&u.y);
        acc[0] += A * f01.x; acc[1] += A * f01.y;
        acc[2] += A * f23.x; acc[3] += A * f23.y;
    } else {
        __half2 hv = *(const __half2*)(h + (size_t)S * 64 + lane * 2);
        float2 f = __half22float2(hv);
        acc[0] += A * f.x; acc[1] += A * f.y;
    }
}

// -------- shared softmax+gather core (packed {ee,src} loads) ------------------
template<int K>
__device__ __forceinline__ void agg_core(float* acc, const __half* __restrict__ h,
                                         const float* __restrict__ ss,
                                         const uint2* __restrict__ pk,
                                         float sdv, int b, int deg,
                                         size_t ebase, int lane)
{
    int bN = b * NPG;
    if (deg <= 32) {
        int src = 0;
        float lg = -1e30f;
        if (lane < deg) {
            uint2 p = pk[ebase + lane];
            src = bN + (int)p.y;
            lg = ss[src] + sdv + __uint_as_float(p.x);
            lg = lg > 0.f ? lg : 0.2f * lg;
        }
        float M = lg;
        #pragma unroll
        for (int o = 16; o; o >>= 1) M = fmaxf(M, __shfl_xor_sync(~0u, M, o));
        float ex = (lane < deg) ? __expf(lg - M) : 0.f;
        float sm = ex;
        #pragma unroll
        for (int o = 16; o; o >>= 1) sm += __shfl_xor_sync(~0u, sm, o);
        float alpha = ex / (sm + 1e-16f);
        for (int j = 0; j < deg; j += 8) {
            #pragma unroll
            for (int q = 0; q < 8; q++) {
                float A = __shfl_sync(~0u, alpha, j + q);
                int S   = __shfl_sync(~0u, src, j + q);
                gatherH<K>(acc, h, S, A, lane);
            }
        }
    } else {
        float m = -1e30f, sm = 0.f;
        for (int i = lane; i < deg; i += 32) {
            uint2 p = pk[ebase + i];
            float lg = ss[bN + (int)p.y] + sdv + __uint_as_float(p.x);
            lg = lg > 0.f ? lg : 0.2f * lg;
            float nm = fmaxf(m, lg);
            sm = sm * __expf(m - nm) + __expf(lg - nm);
            m = nm;
        }
        float M = m;
        #pragma unroll
        for (int o = 16; o; o >>= 1) M = fmaxf(M, __shfl_xor_sync(~0u, M, o));
        sm *= __expf(m - M);
        #pragma unroll
        for (int o = 16; o; o >>= 1) sm += __shfl_xor_sync(~0u, sm, o);
        float inv = 1.f / (sm + 1e-16f);
        for (int basei = 0; basei < deg; basei += 32) {
            int i = basei + lane;
            float alpha = 0.f;
            int src = 0;
            if (i < deg) {
                uint2 p = pk[ebase + i];
                src = bN + (int)p.y;
                float lg = ss[src] + sdv + __uint_as_float(p.x);
                lg = lg > 0.f ? lg : 0.2f * lg;
                alpha = __expf(lg - M) * inv;
            }
            int cnt = min(32, deg - basei);
            for (int j = 0; j < cnt; j += 8) {
                #pragma unroll
                for (int q = 0; q < 8; q++) {
                    float A = __shfl_sync(~0u, alpha, j + q);
                    int S   = __shfl_sync(~0u, src, j + q);
                    gatherH<K>(acc, h, S, A, lane);
                }
            }
        }
    }
}

// -------- agg0 -----------------------------------------------------------------
__global__ void __launch_bounds__(256, 8) k_agg0(const float* __restrict__ bias)
{
    int warp = threadIdx.x >> 5, lane = threadIdx.x & 31;
    int n = blockIdx.x * 8 + warp;
    int b = n / NPG, ln = n - b * NPG;
    int beg = d_beg[ln], deg = d_cnt[ln];
    size_t ebase = (size_t)b * EPG + beg;
    float acc[4] = {0.f, 0.f, 0.f, 0.f};
    if (deg > 0)
        agg_core<4>(acc, d_h0, d_s0s, d_pk0, d_s0d[n], b, deg, ebase, lane);

    float v[4];
    float ps = 0.f, pd = 0.f;
    #pragma unroll
    for (int u = 0; u < 4; u++) {
        float t = acc[u] + bias[lane * 4 + u];
        t = t > 0.f ? t : (__expf(t) - 1.f);
        v[u] = t;
        ps += t * d_was1[lane * 4 + u];
        pd += t * d_wad1[lane * 4 + u];
    }
    #pragma unroll
    for (int o = 16; o; o >>= 1) {
        ps += __shfl_xor_sync(~0u, ps, o);
        pd += __shfl_xor_sync(~0u, pd, o);
    }
    if (lane == 0) { d_s1s[n] = ps; d_s1d[n] = pd; }
    __half2 h01 = __floats2half2_rn(v[0], v[1]);
    __half2 h23 = __floats2half2_rn(v[2], v[3]);
    uint2 u; u.x = *(unsigned*)&h01; u.y = *(unsigned*)&h23;
    *(uint2*)(d_g0h + (size_t)n * 128 + lane * 4) = u;
}

// -------- proj1 via tensor cores ----------------------------------------------
__global__ void k_proj1mma()
{
    __shared__ __half sW[64 * 136];
    __shared__ __half sE[32 * 136];
    int t = threadIdx.x;
    int n0 = blockIdx.x * 32;
    {
        const uint4* src = (const uint4*)d_W1gT;
        uint4* dst = (uint4*)sW;
        for (int i = t; i < 64 * 16; i += 256) {
            int col = i >> 4, ch = i & 15;
            dst[col * 17 + ch] = src[col * 16 + ch];
        }
    }
    {
        const uint4* src = (const uint4*)(d_g0h + (size_t)n0 * 128);
        uint4* dst = (uint4*)sE;
        for (int i = t; i < 32 * 16; i += 256) {
            int row = i >> 4, ch = i & 15;
            dst[row * 17 + ch] = src[row * 16 + ch];
        }
    }
    __syncthreads();

    int warp = t >> 5, lane = t & 31;
    int s = warp & 1;
    int g = warp >> 1;
    int gr = lane >> 2, tc = lane & 3;

    float acc[2][4];
    #pragma unroll
    for (int tt = 0; tt < 2; tt++)
        #pragma unroll
        for (int u = 0; u < 4; u++) acc[tt][u] = 0.f;

    #pragma unroll
    for (int kk = 0; kk < 128; kk += 16) {
        unsigned a0 = *(const unsigned*)(sE + (s * 16 + gr) * 136 + kk + 2 * tc);
        unsigned a1 = *(const unsigned*)(sE + (s * 16 + gr + 8) * 136 + kk + 2 * tc);
        unsigned a2 = *(const unsigned*)(sE + (s * 16 + gr) * 136 + kk + 2 * tc + 8);
        unsigned a3 = *(const unsigned*)(sE + (s * 16 + gr + 8) * 136 + kk + 2 * tc + 8);
        #pragma unroll
        for (int tt = 0; tt < 2; tt++) {
            int col = g * 16 + tt * 8 + gr;
            unsigned b0 = *(const unsigned*)(sW + col * 136 + kk + 2 * tc);
            unsigned b1 = *(const unsigned*)(sW + col * 136 + kk + 2 * tc + 8);
            MMA_FP16(acc[tt], a0, a1, a2, a3, b0, b1);
        }
    }
    #pragma unroll
    for (int tt = 0; tt < 2; tt++) {
        int c = g * 16 + tt * 8 + 2 * tc;
        int r0 = n0 + s * 16 + gr, r1 = r0 + 8;
        __half2 h0 = __floats2half2_rn(acc[tt][0], acc[tt][1]);
        __half2 h1 = __floats2half2_rn(acc[tt][2], acc[tt][3]);
        *(__half2*)(d_h1 + (size_t)r0 * 64 + c) = h0;
        *(__half2*)(d_h1 + (size_t)r1 * 64 + c) = h1;
    }
}

// -------- agg1 fused with pooling partials; emb written fp16 ------------------
__global__ void __launch_bounds__(256, 8) k_agg1(const float* __restrict__ bias)
{
    __shared__ float semb[8][64];
    int warp = threadIdx.x >> 5, lane = threadIdx.x & 31;
    int n = blockIdx.x * 8 + warp;
    int b = n / NPG, ln = n - b * NPG;
    int beg = d_beg[ln], deg = d_cnt[ln];
    size_t ebase = (size_t)b * EPG + beg;
    float acc[2] = {0.f, 0.f};
    if (deg > 0)
        agg_core<2>(acc, d_h1, d_s1s, d_pk1, d_s1d[n], b, deg, ebase, lane);

    float v0 = acc[0] + bias[lane * 2];
    float v1 = acc[1] + bias[lane * 2 + 1];
    __half2 hh = __floats2half2_rn(v0, v1);
    *(__half2*)(d_embh + (size_t)n * 64 + lane * 2) = hh;
    semb[warp][lane * 2] = v0;
    semb[warp][lane * 2 + 1] = v1;
    __syncthreads();
    int t = threadIdx.x;
    if (t < 64) {
        float s = 0.f, m = -1e30f;
        #pragma unroll
        for (int r = 0; r < 8; r++) {
            float x = semb[r][t];
            s += x; m = fmaxf(m, x);
        }
        d_psum[blockIdx.x * 64 + t] = s;
        d_pmaxf[blockIdx.x * 64 + t] = m;
    }
}

// ------ k_ABD ------------------------------------------------------------------
__global__ void k_ABD(const float* __restrict__ W1, const float* __restrict__ b1)
{
    __shared__ __half sW[256 * 72];
    __shared__ __half sE[32 * 72];
    __shared__ float red[256];
    __shared__ float ctx[128];
    int t = threadIdx.x;

    if (blockIdx.x >= 1250) {
        int g = blockIdx.x - 1250;
        int c = t & 63, r = t >> 6;
        float s = 0.f, m = -1e30f;
        for (int i = r; i < 625; i += 4) {
            int idx = (g * 625 + i) * 64 + c;
            s += d_psum[idx];
            m = fmaxf(m, d_pmaxf[idx]);
        }
        red[t] = s;
        __syncthreads();
        if (r < 2) red[t] += red[t + 128];
        __syncthreads();
        if (r == 0) ctx[c] = (red[c] + red[c + 64]) * (1.f / NPG);
        __syncthreads();
        red[t] = m;
        __syncthreads();
        if (r < 2) red[t] = fmaxf(red[t], red[t + 128]);
        __syncthreads();
        if (r == 0) ctx[64 + c] = fmaxf(red[c], red[c + 64]);
        __syncthreads();
        int c2 = t & 127, p = t >> 7;
        float acc = 0.f;
        for (int k = p * 64; k < p * 64 + 64; k++)
            acc += ctx[k] * W1[(144 + k) * 128 + c2];
        red[t] = acc;
        __syncthreads();
        if (p == 0) d_D[g * 128 + c2] = b1[c2] + red[c2] + red[128 + c2];
        return;
    }

    int n0 = blockIdx.x * 32;
    {
        const uint4* src = (const uint4*)d_W1hT;
        uint4* dst = (uint4*)sW;
        for (int i = t; i < 256 * 8; i += 256) {
            int col = i >> 3, ch = i & 7;
            dst[col * 9 + ch] = src[col * 8 + ch];
        }
    }
    {
        const uint4* src = (const uint4*)(d_embh + (size_t)n0 * 64);
        uint4* dst = (uint4*)sE;
        for (int i = t; i < 32 * 8; i += 256) {
            int row = i >> 3, ch = i & 7;
            dst[row * 9 + ch] = src[row * 8 + ch];
        }
    }
    __syncthreads();

    int warp = t >> 5, lane = t & 31;
    int s = warp & 1;
    int g = warp >> 1;
    int gr = lane >> 2, tc = lane & 3;

    float acc[8][4];
    #pragma unroll
    for (int tt = 0; tt < 8; tt++)
        #pragma unroll
        for (int u = 0; u < 4; u++) acc[tt][u] = 0.f;

    #pragma unroll
    for (int kk = 0; kk < 64; kk += 16) {
        unsigned a0 = *(const unsigned*)(sE + (s * 16 + gr) * 72 + kk + 2 * tc);
        unsigned a1 = *(const unsigned*)(sE + (s * 16 + gr + 8) * 72 + kk + 2 * tc);
        unsigned a2 = *(const unsigned*)(sE + (s * 16 + gr) * 72 + kk + 2 * tc + 8);
        unsigned a3 = *(const unsigned*)(sE + (s * 16 + gr + 8) * 72 + kk + 2 * tc + 8);
        #pragma unroll
        for (int tt = 0; tt < 8; tt++) {
            int col = g * 64 + tt * 8 + gr;
            unsigned b0 = *(const unsigned*)(sW + col * 72 + kk + 2 * tc);
            unsigned b1 = *(const unsigned*)(sW + col * 72 + kk + 2 * tc + 8);
            MMA_FP16(acc[tt], a0, a1, a2, a3, b0, b1);
        }
    }
    #pragma unroll
    for (int tt = 0; tt < 8; tt++) {
        int c = g * 64 + tt * 8 + 2 * tc;
        int r0 = n0 + s * 16 + gr, r1 = r0 + 8;
        __half2 h0 = __floats2half2_rn(acc[tt][0], acc[tt][1]);
        __half2 h1 = __floats2half2_rn(acc[tt][2], acc[tt][3]);
        if (c < 128) {
            *(__half2*)(d_A + (size_t)r0 * 128 + c) = h0;
            *(__half2*)(d_A + (size_t)r1 * 128 + c) = h1;
        } else {
            *(__half2*)(d_Bm + (size_t)r0 * 128 + c - 128) = h0;
            *(__half2*)(d_Bm + (size_t)r1 * 128 + c - 128) = h1;
        }
    }
}

// ------ k_final -----------------------------------------------------------------
__global__ void k_final(const float* __restrict__ W2, const float* __restrict__ b2,
                        float* __restrict__ out)
{
    __shared__ __half sEF[8][256];
    __shared__ __half sA[8][16 * 136];
    __shared__ float  sbase[8][128];
    __shared__ float  sV[128];
    int t = threadIdx.x;
    if (t < 128) sV[t] = W2[t];
    __syncthreads();

    int warp = t >> 5, lane = t & 31;
    int gr = lane >> 2, tc = lane & 3;
    float bias2 = b2[0];

    unsigned wb[32];
    #pragma unroll
    for (int q = 0; q < 32; q++) wb[q] = d_WBf[q * 32 + lane];

    __half* myEF = sEF[warp];
    __half* myA  = sA[warp];
    float*  myB  = sbase[warp];

    for (int n = blockIdx.x * 8 + warp; n < NN; n += gridDim.x * 8) {
        int b = n / NPG, ln = n - b * NPG;
        int beg = d_beg[ln], deg = d_cnt[ln];
        if (deg == 0) continue;
        int bNPG = b * NPG;
        size_t bEPG = (size_t)b * EPG;
        size_t ebase = bEPG + beg;

        {
            int j0 = lane * 4;
            uint2 ub = *(const uint2*)(d_Bm + (size_t)n * 128 + j0);
            float2 blo = __half22float2(*(__half2*)&ub.x);
            float2 bhi = __half22float2(*(__half2*)&ub.y);
            float4 vd = *(const float4*)(d_D + b * 128 + j0);
            float4 bs;
            bs.x = blo.x + vd.x; bs.y = blo.y + vd.y;
            bs.z = bhi.x + vd.z; bs.w = bhi.y + vd.w;
            *(float4*)(myB + j0) = bs;
        }
        __syncwarp();

        for (int i = 0; i < deg; i += 16) {
            {
                uint4 v = *(const uint4*)(d_nefp + (ebase + i) * 16 + lane * 8);
                *(uint4*)(myEF + lane * 8) = v;
            }
            int sl = d_srcp[beg + min(i + (lane & 15), deg - 1)];
            __syncwarp();
            #pragma unroll
            for (int j = 0; j < 8; j++) {
                int r = 2 * j + (lane >> 4);
                int sr = __shfl_sync(~0u, sl, r);
                uint4 av = *(const uint4*)(d_A + (size_t)(bNPG + sr) * 128 + (lane & 15) * 8);
                *(uint4*)(myA + r * 136 + (lane & 15) * 8) = av;
            }
            __syncwarp();

            unsigned a0 = *(const unsigned*)(myEF + gr * 16 + 2 * tc);
            unsigned a1 = *(const unsigned*)(myEF + (gr + 8) * 16 + 2 * tc);
            unsigned a2 = *(const unsigned*)(myEF + gr * 16 + 2 * tc + 8);
            unsigned a3 = *(const unsigned*)(myEF + (gr + 8) * 16 + 2 * tc + 8);

            float rowlo = 0.f, rowhi = 0.f;
            #pragma unroll
            for (int nt = 0; nt < 16; nt++) {
                float c[4] = {0.f, 0.f, 0.f, 0.f};
                MMA_FP16(c, a0, a1, a2, a3, wb[nt * 2], wb[nt * 2 + 1]);
                int col = 2 * tc + 8 * nt;
                unsigned alo = *(const unsigned*)(myA + gr * 136 + col);
                unsigned ahi = *(const unsigned*)(myA + (gr + 8) * 136 + col);
                float2 fa = __half22float2(*(__half2*)&alo);
                float2 fh = __half22float2(*(__half2*)&ahi);
                float2 bs = *(const float2*)(myB + col);
                float2 w2 = *(const float2*)(sV + col);
                float v0 = c[0] + fa.x + bs.x;
                float v1 = c[1] + fa.y + bs.y;
                float v2 = c[2] + fh.x + bs.x;
                float v3 = c[3] + fh.y + bs.y;
                rowlo += fmaxf(v0, 0.f) * w2.x + fmaxf(v1, 0.f) * w2.y;
                rowhi += fmaxf(v2, 0.f) * w2.x + fmaxf(v3, 0.f) * w2.y;
            }
            rowlo += __shfl_xor_sync(~0u, rowlo, 1);
            rowlo += __shfl_xor_sync(~0u, rowlo, 2);
            rowhi += __shfl_xor_sync(~0u, rowhi, 1);
            rowhi += __shfl_xor_sync(~0u, rowhi, 2);
            if (tc == 0) {
                int e0 = i + gr, e1 = i + gr + 8;
                if (e0 < deg) out[bEPG + d_csr[beg + e0]] = rowlo + bias2;
                if (e1 < deg) out[bEPG + d_csr[beg + e1]] = rowhi + bias2;
            }
            __syncwarp();
        }
    }
}

// ---------------------------------------------------------------------------
extern "C" void kernel_launch(void* const* d_in, const int* in_sizes, int n_in,
                              void* d_out, int out_size)
{
    const float* node_x    = (const float*)d_in[0];
    const float* edge_attr = (const float*)d_in[1];
    const int*   edge_idx  = (const int*)  d_in[2];
    const float* ln_ng     = (const float*)d_in[3];
    const float* ln_nb     = (const float*)d_in[4];
    const float* ln_eg     = (const float*)d_in[5];
    const float* ln_eb     = (const float*)d_in[6];
    const float* g0_W      = (const float*)d_in[7];
    const float* g0_We     = (const float*)d_in[8];
    const float* g0_asrc   = (const float*)d_in[9];
    const float* g0_adst   = (const float*)d_in[10];
    const float* g0_ae     = (const float*)d_in[11];
    const float* g0_b      = (const float*)d_in[12];
    const float* g1_W      = (const float*)d_in[13];
    const float* g1_We     = (const float*)d_in[14];
    const float* g1_asrc   = (const float*)d_in[15];
    const float* g1_adst   = (const float*)d_in[16];
    const float* g1_ae     = (const float*)d_in[17];
    const float* g1_b      = (const float*)d_in[18];
    const float* mlp_W1    = (const float*)d_in[19];
    const float* mlp_b1    = (const float*)d_in[20];
    const float* mlp_W2    = (const float*)d_in[21];
    const float* mlp_b2    = (const float*)d_in[22];
    float* out = (float*)d_out;

    k_pre<<<148, 256>>>(g0_We, g0_ae, g1_We, g1_ae,
                        g0_W, g0_asrc, g0_adst, g1_W, g1_asrc, g1_adst, mlp_W1);
    k_csr<<<592, 256>>>(edge_idx);
    k_feat<<<7500, 256>>>(edge_attr, ln_eg, ln_eb, node_x, ln_ng, ln_nb, g0_W, edge_idx);
    k_agg0<<<5000, 256>>>(g0_b);
    k_proj1mma<<<NN / 32, 256>>>();
    k_agg1<<<5000, 256>>>(g1_b);
    k_ABD<<<1258, 256>>>(mlp_W1, mlp_b1);
    k_final<<<740, 256>>>(mlp_W2, mlp_b2, out);
}